// round 1
// baseline (speedup 1.0000x reference)
#include <cuda_runtime.h>

// ST-DIM loss: N=512, D=256, C=128, L=144 (12x12 grid)
// loss = mean_{l,n}[ lse_m(preds1[n]·pos[l,m]) - preds1[n]·pos[l,n] ]
//      + mean_{l,n}[ lse_m(preds2[l,n]·pos[l,m]) - preds2[l,n]·pos[l,n] ]
// preds1 = f_t @ W1^T + b1          [512,128]   (location-invariant)
// preds2[l] = loc[l] @ W2^T + b2    [144,512,128]
// pos[l][m][c] = fmap_tp1[m, l, c]  (viewing fmap_tp1 as [N, L, C])

#define PAD 132           // smem tile row stride (floats); keeps float4 alignment
#define FSTRIDE 18432     // 144*128: stride between consecutive n rows of fmap[n,l,c]

__device__ float preds1_g[512 * 128];
__device__ float preds2_g[144l * 512 * 128];
__device__ float loss_part_g[144];

// Load a 128x128 fp32 tile (rows contiguous in k, row pitch = stride floats)
// from global and store k-major transposed into dst[k*PAD + row].
// Global reads fully coalesced (each warp reads one full 512B row).
__device__ __forceinline__ void loadT(float* dst, const float* __restrict__ src,
                                      long stride, int tid) {
#pragma unroll
    for (int it = 0; it < 16; ++it) {
        int f4 = it * 256 + tid;       // 4096 float4s total
        int r  = f4 >> 5;              // row 0..127
        int c  = (f4 & 31) << 2;       // col 0..124 step 4
        float4 v = *reinterpret_cast<const float4*>(src + (long)r * stride + c);
        dst[(c + 0) * PAD + r] = v.x;
        dst[(c + 1) * PAD + r] = v.y;
        dst[(c + 2) * PAD + r] = v.z;
        dst[(c + 3) * PAD + r] = v.w;
    }
}

// 128x128x128 rank-k accumulate: acc[i][j] += sum_k As[k][ty*8+i]*Bs[k][tx*8+j]
__device__ __forceinline__ void mm128(const float* __restrict__ As,
                                      const float* __restrict__ Bs,
                                      int ty, int tx, float acc[8][8]) {
#pragma unroll 4
    for (int k = 0; k < 128; ++k) {
        float a[8], b[8];
        *reinterpret_cast<float4*>(a)     = *reinterpret_cast<const float4*>(&As[k * PAD + ty * 8]);
        *reinterpret_cast<float4*>(a + 4) = *reinterpret_cast<const float4*>(&As[k * PAD + ty * 8 + 4]);
        *reinterpret_cast<float4*>(b)     = *reinterpret_cast<const float4*>(&Bs[k * PAD + tx * 8]);
        *reinterpret_cast<float4*>(b + 4) = *reinterpret_cast<const float4*>(&Bs[k * PAD + tx * 8 + 4]);
#pragma unroll
        for (int i = 0; i < 8; ++i)
#pragma unroll
            for (int j = 0; j < 8; ++j)
                acc[i][j] = fmaf(a[i], b[j], acc[i][j]);
    }
}

// C[128,128] = A[128,K] @ B[128,K]^T + bias, written row-major with pitch 128.
__device__ __forceinline__ void gemm_bias(float* smem,
                                          const float* __restrict__ A, long sa,
                                          const float* __restrict__ B, long sb,
                                          int K, const float* __restrict__ bias,
                                          float* __restrict__ out) {
    float* As = smem;
    float* Bs = smem + 128 * PAD;
    int tid = threadIdx.x, ty = tid >> 4, tx = tid & 15;
    float acc[8][8];
#pragma unroll
    for (int i = 0; i < 8; ++i)
#pragma unroll
        for (int j = 0; j < 8; ++j) acc[i][j] = 0.f;

    for (int k0 = 0; k0 < K; k0 += 128) {
        __syncthreads();
        loadT(As, A + k0, sa, tid);
        loadT(Bs, B + k0, sb, tid);
        __syncthreads();
        mm128(As, Bs, ty, tx, acc);
    }

    float bb[8];
    *reinterpret_cast<float4*>(bb)     = *reinterpret_cast<const float4*>(bias + tx * 8);
    *reinterpret_cast<float4*>(bb + 4) = *reinterpret_cast<const float4*>(bias + tx * 8 + 4);
#pragma unroll
    for (int i = 0; i < 8; ++i) {
        float4 v0 = make_float4(acc[i][0] + bb[0], acc[i][1] + bb[1],
                                acc[i][2] + bb[2], acc[i][3] + bb[3]);
        float4 v1 = make_float4(acc[i][4] + bb[4], acc[i][5] + bb[5],
                                acc[i][6] + bb[6], acc[i][7] + bb[7]);
        *reinterpret_cast<float4*>(out + (ty * 8 + i) * 128 + tx * 8)     = v0;
        *reinterpret_cast<float4*>(out + (ty * 8 + i) * 128 + tx * 8 + 4) = v1;
    }
}

// preds1 = f_t @ W1^T + b1   (4 CTAs of 128 rows, K=256)
__global__ __launch_bounds__(256, 1)
void preds1_kernel(const float* __restrict__ f_t, const float* __restrict__ W1,
                   const float* __restrict__ b1) {
    extern __shared__ float smem[];
    gemm_bias(smem, f_t + (long)blockIdx.x * 128 * 256, 256, W1, 256, 256, b1,
              preds1_g + blockIdx.x * 128 * 128);
}

// preds2[l] = loc[l] @ W2^T + b2  (grid 4 x 144, K=128)
__global__ __launch_bounds__(256, 1)
void preds2_kernel(const float* __restrict__ fmap_t, const float* __restrict__ W2,
                   const float* __restrict__ b2) {
    int nc = blockIdx.x, l = blockIdx.y;
    extern __shared__ float smem[];
    gemm_bias(smem, fmap_t + (long)nc * 128 * FSTRIDE + l * 128, FSTRIDE,
              W2, 128, 128, b2,
              preds2_g + ((long)l * 512 + nc * 128) * 128);
}

// Main fused kernel: one CTA per location l. For each 128-row chunk of the
// combined A = [preds1 (512 rows); preds2[l] (512 rows)], stream pos[l] in
// 128-col tiles, compute logits tile, accumulate sum(exp) and diag per row.
// No max-subtraction needed: |logits| < ~60 so exp stays finite in fp32.
__global__ __launch_bounds__(256, 1)
void stdim_main_kernel(const float* __restrict__ fmap_tp1) {
    extern __shared__ float smem[];
    float* As = smem;
    float* Bs = smem + 128 * PAD;
    int l = blockIdx.x;
    int tid = threadIdx.x, ty = tid >> 4, tx = tid & 15;
    float loss_acc = 0.f;

    for (int nc = 0; nc < 8; ++nc) {
        const float* Asrc = (nc < 4)
            ? (preds1_g + (long)nc * 128 * 128)
            : (preds2_g + ((long)l * 512 + (nc - 4) * 128) * 128);
        loadT(As, Asrc, 128, tid);

        float sume[8], diag[8];
#pragma unroll
        for (int i = 0; i < 8; ++i) { sume[i] = 0.f; diag[i] = 0.f; }

        for (int mc = 0; mc < 4; ++mc) {
            __syncthreads();
            loadT(Bs, fmap_tp1 + (long)mc * 128 * FSTRIDE + l * 128, FSTRIDE, tid);
            __syncthreads();

            float acc[8][8];
#pragma unroll
            for (int i = 0; i < 8; ++i)
#pragma unroll
                for (int j = 0; j < 8; ++j) acc[i][j] = 0.f;

            mm128(As, Bs, ty, tx, acc);

            bool dt = (mc == (nc & 3)) && (ty == tx);
#pragma unroll
            for (int i = 0; i < 8; ++i) {
                float s = 0.f;
#pragma unroll
                for (int j = 0; j < 8; ++j) s += __expf(acc[i][j]);
                sume[i] += s;
                if (dt) diag[i] += acc[i][i];
            }
        }

        // reduce across the 16 threads (half-warp) sharing each row group
#pragma unroll
        for (int off = 1; off < 16; off <<= 1) {
#pragma unroll
            for (int i = 0; i < 8; ++i) {
                sume[i] += __shfl_xor_sync(0xffffffffu, sume[i], off);
                diag[i] += __shfl_xor_sync(0xffffffffu, diag[i], off);
            }
        }
        if (tx == 0) {
#pragma unroll
            for (int i = 0; i < 8; ++i)
                loss_acc += __logf(sume[i]) - diag[i];
        }
        __syncthreads();  // all compute done before As is overwritten next nc
    }

    // deterministic block reduction into per-CTA partial
    smem[tid] = loss_acc;
    __syncthreads();
#pragma unroll
    for (int s = 128; s > 0; s >>= 1) {
        if (tid < s) smem[tid] += smem[tid + s];
        __syncthreads();
    }
    if (tid == 0) loss_part_g[l] = smem[0];
}

__global__ void finalize_kernel(float* __restrict__ out) {
    __shared__ float red[256];
    int tid = threadIdx.x;
    red[tid] = (tid < 144) ? loss_part_g[tid] : 0.f;
    __syncthreads();
#pragma unroll
    for (int s = 128; s > 0; s >>= 1) {
        if (tid < s) red[tid] += red[tid + s];
        __syncthreads();
    }
    if (tid == 0) out[0] = red[0] * (1.0f / 73728.0f);  // /(144*512), both losses
}

extern "C" void kernel_launch(void* const* d_in, const int* in_sizes, int n_in,
                              void* d_out, int out_size) {
    const float* f_t      = (const float*)d_in[0];
    const float* fmap_t   = (const float*)d_in[1];
    const float* fmap_tp1 = (const float*)d_in[2];
    const float* W1       = (const float*)d_in[3];
    const float* b1       = (const float*)d_in[4];
    const float* W2       = (const float*)d_in[5];
    const float* b2       = (const float*)d_in[6];

    int smem = 2 * 128 * PAD * (int)sizeof(float);  // 135168 B
    cudaFuncSetAttribute(preds1_kernel, cudaFuncAttributeMaxDynamicSharedMemorySize, smem);
    cudaFuncSetAttribute(preds2_kernel, cudaFuncAttributeMaxDynamicSharedMemorySize, smem);
    cudaFuncSetAttribute(stdim_main_kernel, cudaFuncAttributeMaxDynamicSharedMemorySize, smem);

    preds1_kernel<<<4, 256, smem>>>(f_t, W1, b1);
    preds2_kernel<<<dim3(4, 144), 256, smem>>>(fmap_t, W2, b2);
    stdim_main_kernel<<<144, 256, smem>>>(fmap_tp1);
    finalize_kernel<<<1, 256>>>((float*)d_out);
}

// round 6
// speedup vs baseline: 1.0108x; 1.0108x over previous
#include <cuda_runtime.h>

// ST-DIM loss: N=512, D=256, C=128, L=144 (12x12 grid)
// R2-R5 resubmit: inner product loops via packed fma.rn.f32x2 (2x fp32 FMA rate).

#define PAD 132           // smem tile row stride (floats); keeps float4 alignment
#define FSTRIDE 18432     // 144*128: stride between consecutive n rows of fmap[n,l,c]

typedef unsigned long long u64;

__device__ float preds1_g[512 * 128];
__device__ float preds2_g[144l * 512 * 128];
__device__ float loss_part_g[144];

__device__ __forceinline__ u64 dup2(float x) {
    u64 r; asm("mov.b64 %0, {%1, %1};" : "=l"(r) : "f"(x)); return r;
}
__device__ __forceinline__ u64 ffma2(u64 a, u64 b, u64 c) {
    u64 d; asm("fma.rn.f32x2 %0, %1, %2, %3;" : "=l"(d) : "l"(a), "l"(b), "l"(c));
    return d;
}
__device__ __forceinline__ float lo32(u64 v) { return __uint_as_float((unsigned)v); }
__device__ __forceinline__ float hi32(u64 v) { return __uint_as_float((unsigned)(v >> 32)); }

// Load a 128x128 fp32 tile (rows contiguous in k, row pitch = stride floats)
// from global and store k-major transposed into dst[k*PAD + row].
__device__ __forceinline__ void loadT(float* dst, const float* __restrict__ src,
                                      long stride, int tid) {
#pragma unroll
    for (int it = 0; it < 16; ++it) {
        int f4 = it * 256 + tid;       // 4096 float4s total
        int r  = f4 >> 5;              // row 0..127
        int c  = (f4 & 31) << 2;       // col 0..124 step 4
        float4 v = *reinterpret_cast<const float4*>(src + (long)r * stride + c);
        dst[(c + 0) * PAD + r] = v.x;
        dst[(c + 1) * PAD + r] = v.y;
        dst[(c + 2) * PAD + r] = v.z;
        dst[(c + 3) * PAD + r] = v.w;
    }
}

// 128x128x128 rank-k accumulate with packed f32x2 FMAs.
// acc2[i][j2] holds (C[i][2*j2], C[i][2*j2+1]) for row ty*8+i, cols tx*8+...
__device__ __forceinline__ void mm128(const float* __restrict__ As,
                                      const float* __restrict__ Bs,
                                      int ty, int tx, u64 acc2[8][4]) {
#pragma unroll 4
    for (int k = 0; k < 128; ++k) {
        float a[8];
        *reinterpret_cast<float4*>(a)     = *reinterpret_cast<const float4*>(&As[k * PAD + ty * 8]);
        *reinterpret_cast<float4*>(a + 4) = *reinterpret_cast<const float4*>(&As[k * PAD + ty * 8 + 4]);
        // B pairs read directly as 64-bit lanes from smem (32B-aligned)
        const u64* bp = reinterpret_cast<const u64*>(&Bs[k * PAD + tx * 8]);
        u64 b2[4];
        b2[0] = bp[0]; b2[1] = bp[1]; b2[2] = bp[2]; b2[3] = bp[3];
        u64 a2[8];
#pragma unroll
        for (int i = 0; i < 8; ++i) a2[i] = dup2(a[i]);
#pragma unroll
        for (int i = 0; i < 8; ++i)
#pragma unroll
            for (int j = 0; j < 4; ++j)
                acc2[i][j] = ffma2(a2[i], b2[j], acc2[i][j]);
    }
}

// C[128,128] = A[128,K] @ B[128,K]^T + bias, written row-major with pitch 128.
__device__ __forceinline__ void gemm_bias(float* smem,
                                          const float* __restrict__ A, long sa,
                                          const float* __restrict__ B, long sb,
                                          int K, const float* __restrict__ bias,
                                          float* __restrict__ out) {
    float* As = smem;
    float* Bs = smem + 128 * PAD;
    int tid = threadIdx.x, ty = tid >> 4, tx = tid & 15;
    u64 acc2[8][4];
#pragma unroll
    for (int i = 0; i < 8; ++i)
#pragma unroll
        for (int j = 0; j < 4; ++j) acc2[i][j] = 0ull;

    for (int k0 = 0; k0 < K; k0 += 128) {
        __syncthreads();
        loadT(As, A + k0, sa, tid);
        loadT(Bs, B + k0, sb, tid);
        __syncthreads();
        mm128(As, Bs, ty, tx, acc2);
    }

    float bb[8];
    *reinterpret_cast<float4*>(bb)     = *reinterpret_cast<const float4*>(bias + tx * 8);
    *reinterpret_cast<float4*>(bb + 4) = *reinterpret_cast<const float4*>(bias + tx * 8 + 4);
#pragma unroll
    for (int i = 0; i < 8; ++i) {
        float4 v0 = make_float4(lo32(acc2[i][0]) + bb[0], hi32(acc2[i][0]) + bb[1],
                                lo32(acc2[i][1]) + bb[2], hi32(acc2[i][1]) + bb[3]);
        float4 v1 = make_float4(lo32(acc2[i][2]) + bb[4], hi32(acc2[i][2]) + bb[5],
                                lo32(acc2[i][3]) + bb[6], hi32(acc2[i][3]) + bb[7]);
        *reinterpret_cast<float4*>(out + (ty * 8 + i) * 128 + tx * 8)     = v0;
        *reinterpret_cast<float4*>(out + (ty * 8 + i) * 128 + tx * 8 + 4) = v1;
    }
}

// preds1 = f_t @ W1^T + b1   (4 CTAs of 128 rows, K=256)
__global__ __launch_bounds__(256, 1)
void preds1_kernel(const float* __restrict__ f_t, const float* __restrict__ W1,
                   const float* __restrict__ b1) {
    extern __shared__ float smem[];
    gemm_bias(smem, f_t + (long)blockIdx.x * 128 * 256, 256, W1, 256, 256, b1,
              preds1_g + blockIdx.x * 128 * 128);
}

// preds2[l] = loc[l] @ W2^T + b2  (grid 4 x 144, K=128)
__global__ __launch_bounds__(256, 1)
void preds2_kernel(const float* __restrict__ fmap_t, const float* __restrict__ W2,
                   const float* __restrict__ b2) {
    int nc = blockIdx.x, l = blockIdx.y;
    extern __shared__ float smem[];
    gemm_bias(smem, fmap_t + (long)nc * 128 * FSTRIDE + l * 128, FSTRIDE,
              W2, 128, 128, b2,
              preds2_g + ((long)l * 512 + nc * 128) * 128);
}

// Main fused kernel: one CTA per location l. For each 128-row chunk of the
// combined A = [preds1 (512 rows); preds2[l] (512 rows)], stream pos[l] in
// 128-col tiles, compute logits tile, accumulate sum(exp) and diag per row.
// No max-subtraction needed: |logits| < ~60 so exp stays finite in fp32.
__global__ __launch_bounds__(256, 1)
void stdim_main_kernel(const float* __restrict__ fmap_tp1) {
    extern __shared__ float smem[];
    float* As = smem;
    float* Bs = smem + 128 * PAD;
    int l = blockIdx.x;
    int tid = threadIdx.x, ty = tid >> 4, tx = tid & 15;
    float loss_acc = 0.f;

    for (int nc = 0; nc < 8; ++nc) {
        const float* Asrc = (nc < 4)
            ? (preds1_g + (long)nc * 128 * 128)
            : (preds2_g + ((long)l * 512 + (nc - 4) * 128) * 128);
        loadT(As, Asrc, 128, tid);

        float sume[8], diag[8];
#pragma unroll
        for (int i = 0; i < 8; ++i) { sume[i] = 0.f; diag[i] = 0.f; }

        for (int mc = 0; mc < 4; ++mc) {
            __syncthreads();
            loadT(Bs, fmap_tp1 + (long)mc * 128 * FSTRIDE + l * 128, FSTRIDE, tid);
            __syncthreads();

            u64 acc2[8][4];
#pragma unroll
            for (int i = 0; i < 8; ++i)
#pragma unroll
                for (int j = 0; j < 4; ++j) acc2[i][j] = 0ull;

            mm128(As, Bs, ty, tx, acc2);

            bool dt = (mc == (nc & 3)) && (ty == tx);
#pragma unroll
            for (int i = 0; i < 8; ++i) {
                float row[8];
#pragma unroll
                for (int j = 0; j < 4; ++j) {
                    row[2 * j]     = lo32(acc2[i][j]);
                    row[2 * j + 1] = hi32(acc2[i][j]);
                }
                float s = 0.f;
#pragma unroll
                for (int j = 0; j < 8; ++j) s += __expf(row[j]);
                sume[i] += s;
                if (dt) diag[i] += row[i];
            }
        }

        // reduce across the 16 threads (half-warp) sharing each row group
#pragma unroll
        for (int off = 1; off < 16; off <<= 1) {
#pragma unroll
            for (int i = 0; i < 8; ++i) {
                sume[i] += __shfl_xor_sync(0xffffffffu, sume[i], off);
                diag[i] += __shfl_xor_sync(0xffffffffu, diag[i], off);
            }
        }
        if (tx == 0) {
#pragma unroll
            for (int i = 0; i < 8; ++i)
                loss_acc += __logf(sume[i]) - diag[i];
        }
        __syncthreads();  // all compute done before As is overwritten next nc
    }

    // deterministic block reduction into per-CTA partial
    smem[tid] = loss_acc;
    __syncthreads();
#pragma unroll
    for (int s = 128; s > 0; s >>= 1) {
        if (tid < s) smem[tid] += smem[tid + s];
        __syncthreads();
    }
    if (tid == 0) loss_part_g[l] = smem[0];
}

__global__ void finalize_kernel(float* __restrict__ out) {
    __shared__ float red[256];
    int tid = threadIdx.x;
    red[tid] = (tid < 144) ? loss_part_g[tid] : 0.f;
    __syncthreads();
#pragma unroll
    for (int s = 128; s > 0; s >>= 1) {
        if (tid < s) red[tid] += red[tid + s];
        __syncthreads();
    }
    if (tid == 0) out[0] = red[0] * (1.0f / 73728.0f);  // /(144*512), both losses
}

extern "C" void kernel_launch(void* const* d_in, const int* in_sizes, int n_in,
                              void* d_out, int out_size) {
    const float* f_t      = (const float*)d_in[0];
    const float* fmap_t   = (const float*)d_in[1];
    const float* fmap_tp1 = (const float*)d_in[2];
    const float* W1       = (const float*)d_in[3];
    const float* b1       = (const float*)d_in[4];
    const float* W2       = (const float*)d_in[5];
    const float* b2       = (const float*)d_in[6];

    int smem = 2 * 128 * PAD * (int)sizeof(float);  // 135168 B
    cudaFuncSetAttribute(preds1_kernel, cudaFuncAttributeMaxDynamicSharedMemorySize, smem);
    cudaFuncSetAttribute(preds2_kernel, cudaFuncAttributeMaxDynamicSharedMemorySize, smem);
    cudaFuncSetAttribute(stdim_main_kernel, cudaFuncAttributeMaxDynamicSharedMemorySize, smem);

    preds1_kernel<<<4, 256, smem>>>(f_t, W1, b1);
    preds2_kernel<<<dim3(4, 144), 256, smem>>>(fmap_t, W2, b2);
    stdim_main_kernel<<<144, 256, smem>>>(fmap_tp1);
    finalize_kernel<<<1, 256>>>((float*)d_out);
}

// round 10
// speedup vs baseline: 2.1907x; 2.1672x over previous
#include <cuda_runtime.h>
#include <cuda_bf16.h>
#include <cstdint>

// ST-DIM loss: N=512, D=256, C=128, L=144.
// R10: logits GEMMs via warp-level mma.sync bf16 (base-target PTX; tcgen05 is
// rejected by this toolchain's sm_103 PTX target). 2-term hi/lo split, 3 MMA
// passes (AhBh + AhBl + AlBh), register accumulators, fused exp/diag epilogue.

#define PAD 132
#define FSTRIDE 18432      // 144*128
#define PITCHB 272         // bf16 tile row pitch in bytes (136 bf16) — ldmatrix conflict-free
typedef unsigned long long u64;

// ---------------- scratch ----------------
__device__ unsigned short p1h_g[512 * 128];
__device__ unsigned short p1l_g[512 * 128];
__device__ unsigned short p2h_g[144l * 512 * 128];
__device__ unsigned short p2l_g[144l * 512 * 128];
__device__ unsigned short posh_g[144l * 512 * 128];
__device__ unsigned short posl_g[144l * 512 * 128];
__device__ float loss_part_g[144];

// ---------------- mma.sync helpers ----------------
__device__ __forceinline__ uint32_t smem_u32(const void* p) {
    uint32_t a;
    asm("{ .reg .u64 t; cvta.to.shared.u64 t, %1; cvt.u32.u64 %0, t; }" : "=r"(a) : "l"(p));
    return a;
}
__device__ __forceinline__ void ldsm_x4(uint32_t r[4], uint32_t addr) {
    asm volatile("ldmatrix.sync.aligned.m8n8.x4.shared.b16 {%0,%1,%2,%3}, [%4];"
        : "=r"(r[0]), "=r"(r[1]), "=r"(r[2]), "=r"(r[3]) : "r"(addr));
}
__device__ __forceinline__ void mma16816(float c[4], const uint32_t a[4], const uint32_t* b) {
    asm volatile("mma.sync.aligned.m16n8k16.row.col.f32.bf16.bf16.f32 "
        "{%0,%1,%2,%3}, {%4,%5,%6,%7}, {%8,%9}, {%0,%1,%2,%3};"
        : "+f"(c[0]), "+f"(c[1]), "+f"(c[2]), "+f"(c[3])
        : "r"(a[0]), "r"(a[1]), "r"(a[2]), "r"(a[3]), "r"(b[0]), "r"(b[1]));
}

// ---------------- fp32 prep helpers (measured-good path) ----------------
__device__ __forceinline__ u64 dup2(float x) {
    u64 r; asm("mov.b64 %0, {%1, %1};" : "=l"(r) : "f"(x)); return r;
}
__device__ __forceinline__ u64 ffma2(u64 a, u64 b, u64 c) {
    u64 d; asm("fma.rn.f32x2 %0, %1, %2, %3;" : "=l"(d) : "l"(a), "l"(b), "l"(c));
    return d;
}
__device__ __forceinline__ float lo32(u64 v) { return __uint_as_float((unsigned)v); }
__device__ __forceinline__ float hi32(u64 v) { return __uint_as_float((unsigned)(v >> 32)); }

__device__ __forceinline__ void loadT(float* dst, const float* __restrict__ src,
                                      long stride, int tid) {
#pragma unroll
    for (int it = 0; it < 16; ++it) {
        int f4 = it * 256 + tid;
        int r  = f4 >> 5;
        int c  = (f4 & 31) << 2;
        float4 v = *reinterpret_cast<const float4*>(src + (long)r * stride + c);
        dst[(c + 0) * PAD + r] = v.x;
        dst[(c + 1) * PAD + r] = v.y;
        dst[(c + 2) * PAD + r] = v.z;
        dst[(c + 3) * PAD + r] = v.w;
    }
}

__device__ __forceinline__ void mm128f(const float* __restrict__ As,
                                       const float* __restrict__ Bs,
                                       int ty, int tx, u64 acc2[8][4]) {
#pragma unroll 4
    for (int k = 0; k < 128; ++k) {
        float a[8];
        *reinterpret_cast<float4*>(a)     = *reinterpret_cast<const float4*>(&As[k * PAD + ty * 8]);
        *reinterpret_cast<float4*>(a + 4) = *reinterpret_cast<const float4*>(&As[k * PAD + ty * 8 + 4]);
        const u64* bp = reinterpret_cast<const u64*>(&Bs[k * PAD + tx * 8]);
        u64 b2[4] = {bp[0], bp[1], bp[2], bp[3]};
        u64 a2[8];
#pragma unroll
        for (int i = 0; i < 8; ++i) a2[i] = dup2(a[i]);
#pragma unroll
        for (int i = 0; i < 8; ++i)
#pragma unroll
            for (int j = 0; j < 4; ++j)
                acc2[i][j] = ffma2(a2[i], b2[j], acc2[i][j]);
    }
}

// C = A@B^T + bias -> bf16 hi/lo split
__device__ __forceinline__ void gemm_bias_split(float* smem,
        const float* __restrict__ A, long sa,
        const float* __restrict__ B, long sb, int K,
        const float* __restrict__ bias,
        unsigned short* __restrict__ oh, unsigned short* __restrict__ ol) {
    float* As = smem;
    float* Bs = smem + 128 * PAD;
    int tid = threadIdx.x, ty = tid >> 4, tx = tid & 15;
    u64 acc2[8][4];
#pragma unroll
    for (int i = 0; i < 8; ++i)
#pragma unroll
        for (int j = 0; j < 4; ++j) acc2[i][j] = 0ull;

    for (int k0 = 0; k0 < K; k0 += 128) {
        __syncthreads();
        loadT(As, A + k0, sa, tid);
        loadT(Bs, B + k0, sb, tid);
        __syncthreads();
        mm128f(As, Bs, ty, tx, acc2);
    }

    float bb[8];
    *reinterpret_cast<float4*>(bb)     = *reinterpret_cast<const float4*>(bias + tx * 8);
    *reinterpret_cast<float4*>(bb + 4) = *reinterpret_cast<const float4*>(bias + tx * 8 + 4);
#pragma unroll
    for (int i = 0; i < 8; ++i) {
        float v[8];
#pragma unroll
        for (int j = 0; j < 4; ++j) {
            v[2 * j]     = lo32(acc2[i][j]) + bb[2 * j];
            v[2 * j + 1] = hi32(acc2[i][j]) + bb[2 * j + 1];
        }
        unsigned short hb[8], lb[8];
#pragma unroll
        for (int j = 0; j < 8; ++j) {
            __nv_bfloat16 h = __float2bfloat16_rn(v[j]);
            hb[j] = __bfloat16_as_ushort(h);
            float r = v[j] - __bfloat162float(h);
            lb[j] = __bfloat16_as_ushort(__float2bfloat16_rn(r));
        }
        long o = (long)(ty * 8 + i) * 128 + tx * 8;
        *reinterpret_cast<uint4*>(oh + o) = *reinterpret_cast<uint4*>(hb);
        *reinterpret_cast<uint4*>(ol + o) = *reinterpret_cast<uint4*>(lb);
    }
}

__global__ __launch_bounds__(256, 1)
void preds1_kernel(const float* __restrict__ f_t, const float* __restrict__ W1,
                   const float* __restrict__ b1) {
    extern __shared__ float smem[];
    gemm_bias_split(smem, f_t + (long)blockIdx.x * 128 * 256, 256, W1, 256, 256, b1,
                    p1h_g + blockIdx.x * 128 * 128, p1l_g + blockIdx.x * 128 * 128);
}

__global__ __launch_bounds__(256, 1)
void preds2_kernel(const float* __restrict__ fmap_t, const float* __restrict__ W2,
                   const float* __restrict__ b2) {
    int nc = blockIdx.x, l = blockIdx.y;
    extern __shared__ float smem[];
    long o = ((long)l * 512 + nc * 128) * 128;
    gemm_bias_split(smem, fmap_t + (long)nc * 128 * FSTRIDE + l * 128, FSTRIDE,
                    W2, 128, 128, b2, p2h_g + o, p2l_g + o);
}

// pos[l][m][c] from fmap_tp1[m, l, c] -> bf16 hi/lo, [l][m][c] contiguous
__global__ __launch_bounds__(256, 1)
void posprep_kernel(const float* __restrict__ fmap_tp1) {
    int l = blockIdx.x, mc = blockIdx.y, tid = threadIdx.x;
#pragma unroll
    for (int it = 0; it < 16; ++it) {
        int g = it * 256 + tid;
        int ml = g >> 5;
        int gp = g & 31;
        int m = mc * 128 + ml;
        float4 v = *reinterpret_cast<const float4*>(fmap_tp1 + (long)m * FSTRIDE + l * 128 + gp * 4);
        float vv[4] = {v.x, v.y, v.z, v.w};
        unsigned short hb[4], lb[4];
#pragma unroll
        for (int j = 0; j < 4; ++j) {
            __nv_bfloat16 h = __float2bfloat16_rn(vv[j]);
            hb[j] = __bfloat16_as_ushort(h);
            lb[j] = __bfloat16_as_ushort(__float2bfloat16_rn(vv[j] - __bfloat162float(h)));
        }
        long o = ((long)l * 512 + m) * 128 + gp * 4;
        *reinterpret_cast<uint2*>(posh_g + o) = *reinterpret_cast<uint2*>(hb);
        *reinterpret_cast<uint2*>(posl_g + o) = *reinterpret_cast<uint2*>(lb);
    }
}

// ---------------- main fused kernel (mma.sync) ----------------
// SMEM: 4 bf16 tiles 128 x 136(pitch), each 34816 B -> 139264 B total.
#define SM_AH 0
#define SM_AL 34816
#define SM_BH 69632
#define SM_BL 104448
#define SM_TOTAL 139264

// copy 128x128 bf16 row-major (pitch 128) -> smem pitch 272B
__device__ __forceinline__ void load_tile(char* sm, const unsigned short* __restrict__ src, int tid) {
#pragma unroll
    for (int it = 0; it < 8; ++it) {
        int g = it * 256 + tid;           // 2048 16B groups
        int row = g >> 4;
        int c16 = g & 15;
        uint4 v = *reinterpret_cast<const uint4*>(src + row * 128 + c16 * 8);
        *reinterpret_cast<uint4*>(sm + row * PITCHB + c16 * 16) = v;
    }
}

__global__ __launch_bounds__(256, 1)
void stdim_main_kernel() {
    extern __shared__ char smc[];
    uint32_t base = smem_u32(smc);
    int l = blockIdx.x;
    int tid = threadIdx.x, wid = tid >> 5, lane = tid & 31;

    // ldmatrix lane address components (byte offsets within a tile)
    // A frag (m16 x k16): tile t = lane/8: row = w*16 + (t&1)*8 + lane%8, k-half = (t>>1)
    uint32_t a_off = (uint32_t)((wid * 16 + ((lane >> 3) & 1) * 8 + (lane & 7)) * PITCHB
                                + ((lane >> 4) & 1) * 16);
    // B pair frag (n16 x k16): tile t: n = jp*16 + (t>>1)*8 + lane%8, k-half = (t&1)
    uint32_t b_row = (uint32_t)(((lane >> 4) & 1) * 8 + (lane & 7));
    uint32_t b_off0 = b_row * PITCHB + ((lane >> 3) & 1) * 16;

    int r0 = wid * 16 + (lane >> 2);   // rows this thread owns within the 128-row chunk
    int q  = lane & 3;                 // col sub-index
    float loss = 0.f;

    for (int nc = 0; nc < 8; ++nc) {
        const unsigned short* ah = (nc < 4) ? (p1h_g + (long)nc * 128 * 128)
                                            : (p2h_g + ((long)l * 512 + (nc - 4) * 128) * 128);
        const unsigned short* al = (nc < 4) ? (p1l_g + (long)nc * 128 * 128)
                                            : (p2l_g + ((long)l * 512 + (nc - 4) * 128) * 128);
        __syncthreads();               // previous iteration's reads of A done
        load_tile(smc + SM_AH, ah, tid);
        load_tile(smc + SM_AL, al, tid);

        float sume0 = 0.f, sume1 = 0.f, dv0 = 0.f, dv1 = 0.f;

        for (int mc = 0; mc < 4; ++mc) {
            __syncthreads();           // previous B reads done
            long bo = ((long)l * 512 + mc * 128) * 128;
            load_tile(smc + SM_BH, posh_g + bo, tid);
            load_tile(smc + SM_BL, posl_g + bo, tid);
            __syncthreads();

            float c[16][4];
#pragma unroll
            for (int j = 0; j < 16; ++j)
#pragma unroll
                for (int e = 0; e < 4; ++e) c[j][e] = 0.f;

            for (int ks = 0; ks < 8; ++ks) {
                uint32_t kb = ks * 32;
                uint32_t a_h[4], a_l[4];
                ldsm_x4(a_h, base + SM_AH + a_off + kb);
                ldsm_x4(a_l, base + SM_AL + a_off + kb);
#pragma unroll
                for (int jp = 0; jp < 8; ++jp) {
                    uint32_t boff = b_off0 + (uint32_t)(jp * 16 * PITCHB) + kb;
                    uint32_t b_h[4], b_l[4];
                    ldsm_x4(b_h, base + SM_BH + boff);
                    ldsm_x4(b_l, base + SM_BL + boff);
                    // ntile 2*jp   : b regs {0,1};  ntile 2*jp+1: {2,3}
                    mma16816(c[2 * jp],     a_h, b_h);
                    mma16816(c[2 * jp],     a_h, b_l);
                    mma16816(c[2 * jp],     a_l, b_h);
                    mma16816(c[2 * jp + 1], a_h, b_h + 2);
                    mma16816(c[2 * jp + 1], a_h, b_l + 2);
                    mma16816(c[2 * jp + 1], a_l, b_h + 2);
                }
            }

            // epilogue on register accumulators
            bool dt = (mc == (nc & 3));
#pragma unroll
            for (int j = 0; j < 16; ++j) {
                int col = j * 8 + q * 2;
                float v0 = c[j][0], v1 = c[j][1], v2 = c[j][2], v3 = c[j][3];
                sume0 += __expf(v0) + __expf(v1);
                sume1 += __expf(v2) + __expf(v3);
                if (dt) {
                    if (col == r0)          dv0 += v0;
                    if (col + 1 == r0)      dv0 += v1;
                    if (col == r0 + 8)      dv1 += v2;
                    if (col + 1 == r0 + 8)  dv1 += v3;
                }
            }
        }

        // reduce row sums / diags across the 4 lanes sharing each row
#pragma unroll
        for (int off = 1; off < 4; off <<= 1) {
            sume0 += __shfl_xor_sync(0xffffffffu, sume0, off);
            sume1 += __shfl_xor_sync(0xffffffffu, sume1, off);
            dv0   += __shfl_xor_sync(0xffffffffu, dv0, off);
            dv1   += __shfl_xor_sync(0xffffffffu, dv1, off);
        }
        if (q == 0)
            loss += (__logf(sume0) - dv0) + (__logf(sume1) - dv1);
    }

    // deterministic block reduction
    __syncthreads();
    float* red = reinterpret_cast<float*>(smc);
    red[tid] = loss;
    __syncthreads();
#pragma unroll
    for (int s = 128; s > 0; s >>= 1) {
        if (tid < s) red[tid] += red[tid + s];
        __syncthreads();
    }
    if (tid == 0) loss_part_g[l] = red[0];
}

__global__ void finalize_kernel(float* __restrict__ out) {
    __shared__ float red[256];
    int tid = threadIdx.x;
    red[tid] = (tid < 144) ? loss_part_g[tid] : 0.f;
    __syncthreads();
#pragma unroll
    for (int s = 128; s > 0; s >>= 1) {
        if (tid < s) red[tid] += red[tid + s];
        __syncthreads();
    }
    if (tid == 0) out[0] = red[0] * (1.0f / 73728.0f);
}

extern "C" void kernel_launch(void* const* d_in, const int* in_sizes, int n_in,
                              void* d_out, int out_size) {
    const float* f_t      = (const float*)d_in[0];
    const float* fmap_t   = (const float*)d_in[1];
    const float* fmap_tp1 = (const float*)d_in[2];
    const float* W1       = (const float*)d_in[3];
    const float* b1       = (const float*)d_in[4];
    const float* W2       = (const float*)d_in[5];
    const float* b2       = (const float*)d_in[6];

    int smem_f = 2 * 128 * PAD * (int)sizeof(float);  // 135168 for fp32 prep GEMMs
    cudaFuncSetAttribute(preds1_kernel, cudaFuncAttributeMaxDynamicSharedMemorySize, smem_f);
    cudaFuncSetAttribute(preds2_kernel, cudaFuncAttributeMaxDynamicSharedMemorySize, smem_f);
    cudaFuncSetAttribute(stdim_main_kernel, cudaFuncAttributeMaxDynamicSharedMemorySize, SM_TOTAL);

    preds1_kernel<<<4, 256, smem_f>>>(f_t, W1, b1);
    preds2_kernel<<<dim3(4, 144), 256, smem_f>>>(fmap_t, W2, b2);
    posprep_kernel<<<dim3(144, 4), 256>>>(fmap_tp1);
    stdim_main_kernel<<<144, 256, SM_TOTAL>>>();
    finalize_kernel<<<1, 256>>>((float*)d_out);
}

// round 13
// speedup vs baseline: 3.5010x; 1.5981x over previous
#include <cuda_runtime.h>
#include <cuda_bf16.h>
#include <cstdint>

// ST-DIM loss: N=512, D=256, C=128, L=144.
// R11-R13: 2-pass bf16 split (A rounded, B=pos hi/lo split) + tensorized prep GEMMs.
// All GEMMs via mma.sync.m16n8k16 bf16 (base-target PTX; tcgen05 unavailable).

#define FSTRIDE 18432      // 144*128
#define PITCHB 272         // bf16 smem tile row pitch in bytes (136 bf16)
typedef unsigned long long u64;

// ---------------- scratch ----------------
__device__ unsigned short p1h_g[512 * 128];                // preds1, bf16
__device__ unsigned short p2h_g[144l * 512 * 128];         // preds2, bf16
__device__ unsigned short posh_g[144l * 512 * 128];        // pos hi
__device__ unsigned short posl_g[144l * 512 * 128];        // pos lo
__device__ float loss_part_g[144];

// ---------------- helpers ----------------
__device__ __forceinline__ uint32_t smem_u32(const void* p) {
    uint32_t a;
    asm("{ .reg .u64 t; cvta.to.shared.u64 t, %1; cvt.u32.u64 %0, t; }" : "=r"(a) : "l"(p));
    return a;
}
__device__ __forceinline__ void ldsm_x4(uint32_t r[4], uint32_t addr) {
    asm volatile("ldmatrix.sync.aligned.m8n8.x4.shared.b16 {%0,%1,%2,%3}, [%4];"
        : "=r"(r[0]), "=r"(r[1]), "=r"(r[2]), "=r"(r[3]) : "r"(addr));
}
__device__ __forceinline__ void mma16816(float c[4], const uint32_t a[4], const uint32_t* b) {
    asm volatile("mma.sync.aligned.m16n8k16.row.col.f32.bf16.bf16.f32 "
        "{%0,%1,%2,%3}, {%4,%5,%6,%7}, {%8,%9}, {%0,%1,%2,%3};"
        : "+f"(c[0]), "+f"(c[1]), "+f"(c[2]), "+f"(c[3])
        : "r"(a[0]), "r"(a[1]), "r"(a[2]), "r"(a[3]), "r"(b[0]), "r"(b[1]));
}
__device__ __forceinline__ unsigned short bf16r(float x) {
    return __bfloat16_as_ushort(__float2bfloat16_rn(x));
}
__device__ __forceinline__ uint32_t pack2(unsigned short a, unsigned short b) {
    return (uint32_t)a | ((uint32_t)b << 16);
}

// copy 128x128 bf16 row-major (pitch 128) -> smem pitch 272B
__device__ __forceinline__ void load_tile(char* sm, const unsigned short* __restrict__ src, int tid) {
#pragma unroll
    for (int it = 0; it < 8; ++it) {
        int g = it * 256 + tid;
        int row = g >> 4;
        int c16 = g & 15;
        uint4 v = *reinterpret_cast<const uint4*>(src + row * 128 + c16 * 8);
        *reinterpret_cast<uint4*>(sm + row * PITCHB + c16 * 16) = v;
    }
}

// 128x128 fp32 tile (row pitch = stride floats) -> bf16 smem (rounded)
__device__ __forceinline__ void load_conv(char* sm, const float* __restrict__ src,
                                          long stride, int tid) {
#pragma unroll
    for (int it = 0; it < 16; ++it) {
        int g = it * 256 + tid;
        int row = g >> 5;
        int gp  = g & 31;
        float4 v = *reinterpret_cast<const float4*>(src + (long)row * stride + gp * 4);
        uint2 o;
        o.x = pack2(bf16r(v.x), bf16r(v.y));
        o.y = pack2(bf16r(v.z), bf16r(v.w));
        *reinterpret_cast<uint2*>(sm + row * PITCHB + gp * 8) = o;
    }
}

// 128x128 fp32 tile -> bf16 hi/lo split smem tiles
__device__ __forceinline__ void load_conv_split(char* smh, char* sml,
                                                const float* __restrict__ src,
                                                long stride, int tid) {
#pragma unroll
    for (int it = 0; it < 16; ++it) {
        int g = it * 256 + tid;
        int row = g >> 5;
        int gp  = g & 31;
        float4 v = *reinterpret_cast<const float4*>(src + (long)row * stride + gp * 4);
        float vv[4] = {v.x, v.y, v.z, v.w};
        unsigned short hb[4], lb[4];
#pragma unroll
        for (int j = 0; j < 4; ++j) {
            hb[j] = bf16r(vv[j]);
            lb[j] = bf16r(vv[j] - __bfloat162float(__ushort_as_bfloat16(hb[j])));
        }
        uint2 oh, ol;
        oh.x = pack2(hb[0], hb[1]); oh.y = pack2(hb[2], hb[3]);
        ol.x = pack2(lb[0], lb[1]); ol.y = pack2(lb[2], lb[3]);
        *reinterpret_cast<uint2*>(smh + row * PITCHB + gp * 8) = oh;
        *reinterpret_cast<uint2*>(sml + row * PITCHB + gp * 8) = ol;
    }
}

// ---------------- tensorized prep GEMM: out = bf16(A @ W^T + bias) ----------------
// A: fp32 [128 x K] row pitch sa; W: fp32 [128 x K] row pitch K; K in {128, 256}.
// SMEM: A @0, WH @34816, WL @69632, bias @104448 (512B)
#define PR_AH 0
#define PR_WH 34816
#define PR_WL 69632
#define PR_B  104448
#define PR_TOTAL 104960

__device__ __forceinline__ void prep_gemm(char* smc, uint32_t base,
        const float* __restrict__ A, long sa,
        const float* __restrict__ W, int K,
        const float* __restrict__ bias,
        unsigned short* __restrict__ out) {
    int tid = threadIdx.x, wid = tid >> 5, lane = tid & 31;

    if (tid < 128) reinterpret_cast<float*>(smc + PR_B)[tid] = bias[tid];

    uint32_t a_off = (uint32_t)((wid * 16 + ((lane >> 3) & 1) * 8 + (lane & 7)) * PITCHB
                                + ((lane >> 4) & 1) * 16);
    uint32_t b_off0 = (uint32_t)((((lane >> 4) & 1) * 8 + (lane & 7)) * PITCHB
                                 + ((lane >> 3) & 1) * 16);

    float c[16][4];
#pragma unroll
    for (int j = 0; j < 16; ++j)
#pragma unroll
        for (int e = 0; e < 4; ++e) c[j][e] = 0.f;

    for (int k0 = 0; k0 < K; k0 += 128) {
        __syncthreads();
        load_conv(smc + PR_AH, A + k0, sa, tid);
        load_conv_split(smc + PR_WH, smc + PR_WL, W + k0, K, tid);
        __syncthreads();

        for (int ks = 0; ks < 8; ++ks) {
            uint32_t kb = ks * 32;
            uint32_t a[4];
            ldsm_x4(a, base + PR_AH + a_off + kb);
#pragma unroll
            for (int jp = 0; jp < 8; ++jp) {
                uint32_t boff = b_off0 + (uint32_t)(jp * 16 * PITCHB) + kb;
                uint32_t b_h[4], b_l[4];
                ldsm_x4(b_h, base + PR_WH + boff);
                ldsm_x4(b_l, base + PR_WL + boff);
                mma16816(c[2 * jp],     a, b_h);
                mma16816(c[2 * jp],     a, b_l);
                mma16816(c[2 * jp + 1], a, b_h + 2);
                mma16816(c[2 * jp + 1], a, b_l + 2);
            }
        }
    }

    const float* sb = reinterpret_cast<const float*>(smc + PR_B);
    int r0 = wid * 16 + (lane >> 2);
    int q  = lane & 3;
#pragma unroll
    for (int j = 0; j < 16; ++j) {
        int col = j * 8 + q * 2;
        float b0 = sb[col], b1v = sb[col + 1];
        uint32_t p0 = pack2(bf16r(c[j][0] + b0), bf16r(c[j][1] + b1v));
        uint32_t p1 = pack2(bf16r(c[j][2] + b0), bf16r(c[j][3] + b1v));
        *reinterpret_cast<uint32_t*>(out + (long)r0 * 128 + col)       = p0;
        *reinterpret_cast<uint32_t*>(out + (long)(r0 + 8) * 128 + col) = p1;
    }
}

__global__ __launch_bounds__(256, 1)
void preds1_kernel(const float* __restrict__ f_t, const float* __restrict__ W1,
                   const float* __restrict__ b1) {
    extern __shared__ char smc[];
    prep_gemm(smc, smem_u32(smc), f_t + (long)blockIdx.x * 128 * 256, 256,
              W1, 256, b1, p1h_g + (long)blockIdx.x * 128 * 128);
}

__global__ __launch_bounds__(256, 1)
void preds2_kernel(const float* __restrict__ fmap_t, const float* __restrict__ W2,
                   const float* __restrict__ b2) {
    int nc = blockIdx.x, l = blockIdx.y;
    extern __shared__ char smc[];
    prep_gemm(smc, smem_u32(smc),
              fmap_t + (long)nc * 128 * FSTRIDE + l * 128, FSTRIDE,
              W2, 128, b2, p2h_g + ((long)l * 512 + nc * 128) * 128);
}

// pos[l][m][c] from fmap_tp1[m, l, c] -> bf16 hi/lo, [l][m][c] contiguous
__global__ __launch_bounds__(256, 1)
void posprep_kernel(const float* __restrict__ fmap_tp1) {
    int l = blockIdx.x, mc = blockIdx.y, tid = threadIdx.x;
#pragma unroll
    for (int it = 0; it < 16; ++it) {
        int g = it * 256 + tid;
        int ml = g >> 5;
        int gp = g & 31;
        int m = mc * 128 + ml;
        float4 v = *reinterpret_cast<const float4*>(fmap_tp1 + (long)m * FSTRIDE + l * 128 + gp * 4);
        float vv[4] = {v.x, v.y, v.z, v.w};
        unsigned short hb[4], lb[4];
#pragma unroll
        for (int j = 0; j < 4; ++j) {
            hb[j] = bf16r(vv[j]);
            lb[j] = bf16r(vv[j] - __bfloat162float(__ushort_as_bfloat16(hb[j])));
        }
        long o = ((long)l * 512 + m) * 128 + gp * 4;
        uint2 oh, ol;
        oh.x = pack2(hb[0], hb[1]); oh.y = pack2(hb[2], hb[3]);
        ol.x = pack2(lb[0], lb[1]); ol.y = pack2(lb[2], lb[3]);
        *reinterpret_cast<uint2*>(posh_g + o) = oh;
        *reinterpret_cast<uint2*>(posl_g + o) = ol;
    }
}

// ---------------- main fused kernel: 2-pass (A bf16, B hi/lo) ----------------
#define SM_AH 0
#define SM_BH 34816
#define SM_BL 69632
#define SM_TOTAL 104448

__global__ __launch_bounds__(256, 1)
void stdim_main_kernel() {
    extern __shared__ char smc[];
    uint32_t base = smem_u32(smc);
    int l = blockIdx.x;
    int tid = threadIdx.x, wid = tid >> 5, lane = tid & 31;

    uint32_t a_off = (uint32_t)((wid * 16 + ((lane >> 3) & 1) * 8 + (lane & 7)) * PITCHB
                                + ((lane >> 4) & 1) * 16);
    uint32_t b_off0 = (uint32_t)((((lane >> 4) & 1) * 8 + (lane & 7)) * PITCHB
                                 + ((lane >> 3) & 1) * 16);

    int r0 = wid * 16 + (lane >> 2);
    int q  = lane & 3;
    float loss = 0.f;

    for (int nc = 0; nc < 8; ++nc) {
        const unsigned short* ah = (nc < 4) ? (p1h_g + (long)nc * 128 * 128)
                                            : (p2h_g + ((long)l * 512 + (nc - 4) * 128) * 128);
        __syncthreads();
        load_tile(smc + SM_AH, ah, tid);

        float sume0 = 0.f, sume1 = 0.f, dv0 = 0.f, dv1 = 0.f;

        for (int mc = 0; mc < 4; ++mc) {
            __syncthreads();
            long bo = ((long)l * 512 + mc * 128) * 128;
            load_tile(smc + SM_BH, posh_g + bo, tid);
            load_tile(smc + SM_BL, posl_g + bo, tid);
            __syncthreads();

            float c[16][4];
#pragma unroll
            for (int j = 0; j < 16; ++j)
#pragma unroll
                for (int e = 0; e < 4; ++e) c[j][e] = 0.f;

            for (int ks = 0; ks < 8; ++ks) {
                uint32_t kb = ks * 32;
                uint32_t a[4];
                ldsm_x4(a, base + SM_AH + a_off + kb);
#pragma unroll
                for (int jp = 0; jp < 8; ++jp) {
                    uint32_t boff = b_off0 + (uint32_t)(jp * 16 * PITCHB) + kb;
                    uint32_t b_h[4], b_l[4];
                    ldsm_x4(b_h, base + SM_BH + boff);
                    ldsm_x4(b_l, base + SM_BL + boff);
                    mma16816(c[2 * jp],     a, b_h);
                    mma16816(c[2 * jp],     a, b_l);
                    mma16816(c[2 * jp + 1], a, b_h + 2);
                    mma16816(c[2 * jp + 1], a, b_l + 2);
                }
            }

            bool dt = (mc == (nc & 3));
#pragma unroll
            for (int j = 0; j < 16; ++j) {
                int col = j * 8 + q * 2;
                float v0 = c[j][0], v1 = c[j][1], v2 = c[j][2], v3 = c[j][3];
                sume0 += __expf(v0) + __expf(v1);
                sume1 += __expf(v2) + __expf(v3);
                if (dt) {
                    if (col == r0)          dv0 += v0;
                    if (col + 1 == r0)      dv0 += v1;
                    if (col == r0 + 8)      dv1 += v2;
                    if (col + 1 == r0 + 8)  dv1 += v3;
                }
            }
        }

#pragma unroll
        for (int off = 1; off < 4; off <<= 1) {
            sume0 += __shfl_xor_sync(0xffffffffu, sume0, off);
            sume1 += __shfl_xor_sync(0xffffffffu, sume1, off);
            dv0   += __shfl_xor_sync(0xffffffffu, dv0, off);
            dv1   += __shfl_xor_sync(0xffffffffu, dv1, off);
        }
        if (q == 0)
            loss += (__logf(sume0) - dv0) + (__logf(sume1) - dv1);
    }

    __syncthreads();
    float* red = reinterpret_cast<float*>(smc);
    red[tid] = loss;
    __syncthreads();
#pragma unroll
    for (int s = 128; s > 0; s >>= 1) {
        if (tid < s) red[tid] += red[tid + s];
        __syncthreads();
    }
    if (tid == 0) loss_part_g[l] = red[0];
}

__global__ void finalize_kernel(float* __restrict__ out) {
    __shared__ float red[256];
    int tid = threadIdx.x;
    red[tid] = (tid < 144) ? loss_part_g[tid] : 0.f;
    __syncthreads();
#pragma unroll
    for (int s = 128; s > 0; s >>= 1) {
        if (tid < s) red[tid] += red[tid + s];
        __syncthreads();
    }
    if (tid == 0) out[0] = red[0] * (1.0f / 73728.0f);
}

extern "C" void kernel_launch(void* const* d_in, const int* in_sizes, int n_in,
                              void* d_out, int out_size) {
    const float* f_t      = (const float*)d_in[0];
    const float* fmap_t   = (const float*)d_in[1];
    const float* fmap_tp1 = (const float*)d_in[2];
    const float* W1       = (const float*)d_in[3];
    const float* b1       = (const float*)d_in[4];
    const float* W2       = (const float*)d_in[5];
    const float* b2       = (const float*)d_in[6];

    cudaFuncSetAttribute(preds1_kernel, cudaFuncAttributeMaxDynamicSharedMemorySize, PR_TOTAL);
    cudaFuncSetAttribute(preds2_kernel, cudaFuncAttributeMaxDynamicSharedMemorySize, PR_TOTAL);
    cudaFuncSetAttribute(stdim_main_kernel, cudaFuncAttributeMaxDynamicSharedMemorySize, SM_TOTAL);

    preds1_kernel<<<4, 256, PR_TOTAL>>>(f_t, W1, b1);
    preds2_kernel<<<dim3(4, 144), 256, PR_TOTAL>>>(fmap_t, W2, b2);
    posprep_kernel<<<dim3(144, 4), 256>>>(fmap_tp1);
    stdim_main_kernel<<<144, 256, SM_TOTAL>>>();
    finalize_kernel<<<1, 256>>>((float*)d_out);
}